// round 1
// baseline (speedup 1.0000x reference)
#include <cuda_runtime.h>
#include <math_constants.h>

#define MAXN 50000
#define MAXE 500000
#define C    128
#define RELS 3

// ---------------- scratch (static device memory; no allocation) ----------------
__device__ float g_xw[(size_t)RELS * MAXN * C];   // per-relation transformed feats
__device__ float g_h[(size_t)MAXN * C];           // layer-1 output
__device__ float g_alpha[MAXE];                   // per-edge logits (post leaky-relu)
__device__ float g_sq[RELS * MAXN];               // per-(rel,node) q-projection scalar
__device__ float g_sk[RELS * MAXN];               // per-(rel,node) k-projection scalar
__device__ float g_wq[RELS * C];                  // w[r] @ q
__device__ float g_wk[RELS * C];                  // w[r] @ k
__device__ float g_cattr;                         // le . e
__device__ int   g_deg[MAXN];
__device__ int   g_incl[MAXN];
__device__ int   g_indptr[MAXN + 1];
__device__ int   g_cursor[MAXN];
__device__ int   g_eidx[MAXE];
__device__ int   g_bsum[64];

// ---------------- CSR build ----------------
__global__ void k_zero_deg(int n) {
    int i = blockIdx.x * blockDim.x + threadIdx.x;
    if (i < n) g_deg[i] = 0;
}

__global__ void k_count(const int* __restrict__ dst, int e_cnt) {
    int e = blockIdx.x * blockDim.x + threadIdx.x;
    if (e < e_cnt) atomicAdd(&g_deg[dst[e]], 1);
}

__global__ void k_scanA(int n) {
    __shared__ int sh[2][1024];
    int tid = threadIdx.x;
    int i = blockIdx.x * 1024 + tid;
    int v = (i < n) ? g_deg[i] : 0;
    sh[0][tid] = v;
    __syncthreads();
    int pb = 0;
#pragma unroll
    for (int off = 1; off < 1024; off <<= 1) {
        int nb = pb ^ 1;
        int val = sh[pb][tid];
        if (tid >= off) val += sh[pb][tid - off];
        sh[nb][tid] = val;
        pb = nb;
        __syncthreads();
    }
    int incl = sh[pb][tid];
    if (i < n) g_incl[i] = incl;
    if (tid == 1023) g_bsum[blockIdx.x] = incl;
}

__global__ void k_scanB(int nblk) {
    if (threadIdx.x == 0 && blockIdx.x == 0) {
        int run = 0;
        for (int b = 0; b < nblk; ++b) {
            int t = g_bsum[b];
            g_bsum[b] = run;
            run += t;
        }
    }
}

__global__ void k_scanC(int n) {
    int i = blockIdx.x * blockDim.x + threadIdx.x;
    if (i < n) {
        int total = g_incl[i] + g_bsum[i >> 10];
        g_indptr[i + 1] = total;
        g_cursor[i] = total - g_deg[i];
        if (i == 0) g_indptr[0] = 0;
    }
}

__global__ void k_fill(const int* __restrict__ dst, int e_cnt) {
    int e = blockIdx.x * blockDim.x + threadIdx.x;
    if (e < e_cnt) {
        int pos = atomicAdd(&g_cursor[dst[e]], 1);
        g_eidx[pos] = e;
    }
}

// ---------------- per-layer small precompute: wq = w[r]@q, wk = w[r]@k, cattr = le.e ----------------
__global__ void k_prep(const float* __restrict__ w, const float* __restrict__ q,
                       const float* __restrict__ kk, const float* __restrict__ le,
                       const float* __restrict__ ee) {
    int t = threadIdx.x;
    if (t < RELS * C) {
        const float* row = w + (size_t)t * C;   // w[r][i][:] with t = r*C + i
        float aq = 0.f, ak = 0.f;
#pragma unroll 8
        for (int o = 0; o < C; ++o) {
            float wv = row[o];
            aq += wv * q[o];
            ak += wv * kk[o];
        }
        g_wq[t] = aq;
        g_wk[t] = ak;
    } else if (t < RELS * C + 32) {
        int lane = t - RELS * C;
        float p = 0.f;
        for (int o = lane; o < C; o += 32) p += le[o] * ee[o];
#pragma unroll
        for (int off = 16; off; off >>= 1) p += __shfl_xor_sync(0xffffffffu, p, off);
        if (lane == 0) g_cattr = p;
    }
}

// ---------------- per-node attention scalars: sq[r,n] = x[n].wq[r], sk[r,n] = x[n].wk[r] ----------------
__global__ void k_sqk(const float* __restrict__ x, int n) {
    int gw = (blockIdx.x * blockDim.x + threadIdx.x) >> 5;
    int lane = threadIdx.x & 31;
    if (gw >= n) return;
    float4 xv = ((const float4*)x)[(size_t)gw * 32 + lane];
    float aq[RELS], ak[RELS];
#pragma unroll
    for (int r = 0; r < RELS; ++r) {
        float4 wqv = ((const float4*)g_wq)[r * 32 + lane];
        float4 wkv = ((const float4*)g_wk)[r * 32 + lane];
        aq[r] = xv.x * wqv.x + xv.y * wqv.y + xv.z * wqv.z + xv.w * wqv.w;
        ak[r] = xv.x * wkv.x + xv.y * wkv.y + xv.z * wkv.z + xv.w * wkv.w;
    }
#pragma unroll
    for (int off = 16; off; off >>= 1) {
#pragma unroll
        for (int r = 0; r < RELS; ++r) {
            aq[r] += __shfl_xor_sync(0xffffffffu, aq[r], off);
            ak[r] += __shfl_xor_sync(0xffffffffu, ak[r], off);
        }
    }
    if (lane == 0) {
#pragma unroll
        for (int r = 0; r < RELS; ++r) {
            g_sq[r * n + gw] = aq[r];
            g_sk[r * n + gw] = ak[r];
        }
    }
}

// ---------------- GEMM: g_xw[r] = X (n x 128) @ W[r] (128 x 128) ----------------
// block: 256 threads, BM=128 rows, full 128 cols, BK=32 chunks, 8x8 per-thread tile
__global__ __launch_bounds__(256, 2) void k_gemm(const float* __restrict__ X,
                                                 const float* __restrict__ W, int n) {
    const int BK = 32;
    __shared__ float As[BK][132];   // transposed A tile: As[k][m], padded
    __shared__ float Bs[BK][128];

    int r = blockIdx.y;
    int m0 = blockIdx.x * 128;
    const float* Wr = W + (size_t)r * C * C;
    float* Cr = g_xw + ((size_t)r * n + m0) * C;

    int tid = threadIdx.x;
    int tx = tid & 15, ty = tid >> 4;

    float acc[8][8];
#pragma unroll
    for (int i = 0; i < 8; ++i)
#pragma unroll
        for (int j = 0; j < 8; ++j) acc[i][j] = 0.f;

    for (int kc = 0; kc < C; kc += BK) {
        // load A tile (transposed into As[k][m])
#pragma unroll
        for (int t = 0; t < 4; ++t) {
            int row = (tid >> 3) + t * 32;
            int kofs = (tid & 7) << 2;
            float4 v = make_float4(0.f, 0.f, 0.f, 0.f);
            if (m0 + row < n)
                v = *(const float4*)(X + (size_t)(m0 + row) * C + kc + kofs);
            As[kofs + 0][row] = v.x;
            As[kofs + 1][row] = v.y;
            As[kofs + 2][row] = v.z;
            As[kofs + 3][row] = v.w;
        }
        // load B tile
#pragma unroll
        for (int t = 0; t < 4; ++t) {
            int kkx = (tid >> 5) + t * 8;
            int col = (tid & 31) << 2;
            *(float4*)&Bs[kkx][col] = *(const float4*)(Wr + (size_t)(kc + kkx) * C + col);
        }
        __syncthreads();
#pragma unroll
        for (int k = 0; k < BK; ++k) {
            float a[8], b[8];
            *(float4*)(a)     = *(const float4*)&As[k][ty * 8];
            *(float4*)(a + 4) = *(const float4*)&As[k][ty * 8 + 4];
            *(float4*)(b)     = *(const float4*)&Bs[k][tx * 8];
            *(float4*)(b + 4) = *(const float4*)&Bs[k][tx * 8 + 4];
#pragma unroll
            for (int i = 0; i < 8; ++i)
#pragma unroll
                for (int j = 0; j < 8; ++j) acc[i][j] = fmaf(a[i], b[j], acc[i][j]);
        }
        __syncthreads();
    }
#pragma unroll
    for (int i = 0; i < 8; ++i) {
        int row = m0 + ty * 8 + i;
        if (row < n) {
            float* crow = Cr + (size_t)(ty * 8 + i) * C + tx * 8;
            *(float4*)(crow)     = make_float4(acc[i][0], acc[i][1], acc[i][2], acc[i][3]);
            *(float4*)(crow + 4) = make_float4(acc[i][4], acc[i][5], acc[i][6], acc[i][7]);
        }
    }
}

// ---------------- per-edge attention logits ----------------
__global__ void k_alpha(const int* __restrict__ src, const int* __restrict__ dst,
                        const int* __restrict__ etype, const float* __restrict__ attr,
                        int n, int e_cnt) {
    int e = blockIdx.x * blockDim.x + threadIdx.x;
    if (e >= e_cnt) return;
    int r = etype[e];
    float a = g_sq[r * n + dst[e]] + g_sk[r * n + src[e]] + g_cattr * attr[e];
    g_alpha[e] = (a > 0.f) ? a : 0.2f * a;
}

// ---------------- per-node softmax + weighted aggregation (warp per node) ----------------
__global__ void k_agg(const int* __restrict__ src, const int* __restrict__ etype,
                      const float* __restrict__ bias, float* __restrict__ out,
                      int relu, int n) {
    int gw = (blockIdx.x * blockDim.x + threadIdx.x) >> 5;
    int lane = threadIdx.x & 31;
    if (gw >= n) return;
    int beg = g_indptr[gw], end = g_indptr[gw + 1];

    // pass 1: max over incoming-edge logits
    float m = -CUDART_INF_F;
    for (int j = beg + lane; j < end; j += 32) m = fmaxf(m, g_alpha[g_eidx[j]]);
#pragma unroll
    for (int off = 16; off; off >>= 1) m = fmaxf(m, __shfl_xor_sync(0xffffffffu, m, off));

    // pass 2: sum of exp
    float s = 0.f;
    for (int j = beg + lane; j < end; j += 32) s += __expf(g_alpha[g_eidx[j]] - m);
#pragma unroll
    for (int off = 16; off; off >>= 1) s += __shfl_xor_sync(0xffffffffu, s, off);
    float inv = 1.f / (s + 1e-16f);

    // pass 3: weighted gather of transformed source features
    float4 acc = make_float4(0.f, 0.f, 0.f, 0.f);
    for (int j = beg; j < end; ++j) {
        int e = g_eidx[j];
        float coeff = __expf(g_alpha[e] - m) * inv;
        int sv = src[e];
        int r = etype[e];
        const float4* row = (const float4*)(g_xw + ((size_t)r * n + sv) * C);
        float4 v = row[lane];
        acc.x = fmaf(coeff, v.x, acc.x);
        acc.y = fmaf(coeff, v.y, acc.y);
        acc.z = fmaf(coeff, v.z, acc.z);
        acc.w = fmaf(coeff, v.w, acc.w);
    }
    float4 bb = ((const float4*)bias)[lane];
    acc.x += bb.x; acc.y += bb.y; acc.z += bb.z; acc.w += bb.w;
    if (relu) {
        acc.x = fmaxf(acc.x, 0.f); acc.y = fmaxf(acc.y, 0.f);
        acc.z = fmaxf(acc.z, 0.f); acc.w = fmaxf(acc.w, 0.f);
    }
    ((float4*)(out + (size_t)gw * C))[lane] = acc;
}

// ---------------- driver ----------------
static void run_layer(const float* xin, const float* w, const float* q, const float* kk,
                      const float* le, const float* ee, const float* b,
                      const int* src, const int* dst, const int* etype, const float* attr,
                      float* xout, int relu, int n, int e_cnt) {
    k_prep<<<1, 512>>>(w, q, kk, le, ee);
    k_sqk<<<(n + 7) / 8, 256>>>(xin, n);
    dim3 gg((n + 127) / 128, RELS);
    k_gemm<<<gg, 256>>>(xin, w, n);
    k_alpha<<<(e_cnt + 255) / 256, 256>>>(src, dst, etype, attr, n, e_cnt);
    k_agg<<<(n + 7) / 8, 256>>>(src, etype, b, xout, relu, n);
}

extern "C" void kernel_launch(void* const* d_in, const int* in_sizes, int n_in,
                              void* d_out, int out_size) {
    const float* x    = (const float*)d_in[0];
    const int*   ei   = (const int*)d_in[1];
    const int*   et   = (const int*)d_in[2];
    const float* attr = (const float*)d_in[3];
    const float *w1 = (const float*)d_in[4],  *q1 = (const float*)d_in[5],
                *k1 = (const float*)d_in[6],  *le1 = (const float*)d_in[7],
                *e1 = (const float*)d_in[8],  *b1 = (const float*)d_in[9];
    const float *w2 = (const float*)d_in[10], *q2 = (const float*)d_in[11],
                *k2 = (const float*)d_in[12], *le2 = (const float*)d_in[13],
                *e2 = (const float*)d_in[14], *b2 = (const float*)d_in[15];

    int n = in_sizes[0] / C;
    int e_cnt = in_sizes[2];
    const int* src = ei;
    const int* dst = ei + e_cnt;

    // CSR by destination (shared by both layers)
    k_zero_deg<<<(n + 255) / 256, 256>>>(n);
    k_count<<<(e_cnt + 255) / 256, 256>>>(dst, e_cnt);
    int nblk = (n + 1023) / 1024;
    k_scanA<<<nblk, 1024>>>(n);
    k_scanB<<<1, 32>>>(nblk);
    k_scanC<<<(n + 255) / 256, 256>>>(n);
    k_fill<<<(e_cnt + 255) / 256, 256>>>(dst, e_cnt);

    float* h = nullptr;
    cudaGetSymbolAddress((void**)&h, g_h);

    run_layer(x, w1, q1, k1, le1, e1, b1, src, dst, et, attr, h, 1, n, e_cnt);
    run_layer(h, w2, q2, k2, le2, e2, b2, src, dst, et, attr, (float*)d_out, 0, n, e_cnt);
}

// round 2
// speedup vs baseline: 1.1307x; 1.1307x over previous
#include <cuda_runtime.h>
#include <math_constants.h>

#define MAXN 50000
#define MAXE 500000
#define C    128
#define RELS 3

// ---------------- scratch (static device memory; no allocation) ----------------
__device__ __align__(16) float g_xw[(size_t)RELS * MAXN * C];   // per-relation transformed feats
__device__ __align__(16) float g_h[(size_t)MAXN * C];           // layer-1 output
__device__ float g_alpha[MAXE];                   // per-edge logits (post leaky-relu)
__device__ float g_sq[RELS * MAXN];               // per-(rel,node) q-projection scalar
__device__ float g_sk[RELS * MAXN];               // per-(rel,node) k-projection scalar
__device__ __align__(16) float g_wq[RELS * C];    // w[r] @ q
__device__ __align__(16) float g_wk[RELS * C];    // w[r] @ k
__device__ float g_cattr;                         // le . e
__device__ int   g_deg[MAXN];
__device__ int   g_incl[MAXN];
__device__ int   g_indptr[MAXN + 1];
__device__ int   g_cursor[MAXN];
__device__ int   g_eidx[MAXE];
__device__ int   g_bsum[64];

union F4U2 { float4 f; unsigned long long u[2]; };

// ---------------- CSR build ----------------
__global__ void k_zero_deg(int n) {
    int i = blockIdx.x * blockDim.x + threadIdx.x;
    if (i < n) g_deg[i] = 0;
}

__global__ void k_count(const int* __restrict__ dst, int e_cnt) {
    int e = blockIdx.x * blockDim.x + threadIdx.x;
    if (e < e_cnt) atomicAdd(&g_deg[dst[e]], 1);
}

__global__ void k_scanA(int n) {
    __shared__ int sh[2][1024];
    int tid = threadIdx.x;
    int i = blockIdx.x * 1024 + tid;
    int v = (i < n) ? g_deg[i] : 0;
    sh[0][tid] = v;
    __syncthreads();
    int pb = 0;
#pragma unroll
    for (int off = 1; off < 1024; off <<= 1) {
        int nb = pb ^ 1;
        int val = sh[pb][tid];
        if (tid >= off) val += sh[pb][tid - off];
        sh[nb][tid] = val;
        pb = nb;
        __syncthreads();
    }
    int incl = sh[pb][tid];
    if (i < n) g_incl[i] = incl;
    if (tid == 1023) g_bsum[blockIdx.x] = incl;
}

// parallel block-sum scan (nblk <= 64) -> exclusive offsets in g_bsum
__global__ void k_scanB(int nblk) {
    __shared__ int sh[64];
    int t = threadIdx.x;                 // 64 threads
    int v = (t < nblk) ? g_bsum[t] : 0;
    sh[t] = v;
    __syncthreads();
#pragma unroll
    for (int off = 1; off < 64; off <<= 1) {
        int add = (t >= off) ? sh[t - off] : 0;
        __syncthreads();
        sh[t] += add;
        __syncthreads();
    }
    if (t < nblk) g_bsum[t] = sh[t] - v;   // exclusive
}

__global__ void k_scanC(int n) {
    int i = blockIdx.x * blockDim.x + threadIdx.x;
    if (i < n) {
        int total = g_incl[i] + g_bsum[i >> 10];
        g_indptr[i + 1] = total;
        g_cursor[i] = total - g_deg[i];
        if (i == 0) g_indptr[0] = 0;
    }
}

__global__ void k_fill(const int* __restrict__ dst, int e_cnt) {
    int e = blockIdx.x * blockDim.x + threadIdx.x;
    if (e < e_cnt) {
        int pos = atomicAdd(&g_cursor[dst[e]], 1);
        g_eidx[pos] = e;
    }
}

// ---------------- per-layer precompute: wq = w[r]@q, wk = w[r]@k, cattr = le.e ----------------
// warp per output row
__global__ void k_prep(const float* __restrict__ w, const float* __restrict__ q,
                       const float* __restrict__ kk, const float* __restrict__ le,
                       const float* __restrict__ ee) {
    int gw = (blockIdx.x * blockDim.x + threadIdx.x) >> 5;
    int lane = threadIdx.x & 31;
    if (gw < RELS * C) {
        const float4* row = (const float4*)(w + (size_t)gw * C);
        float4 wv = row[lane];
        float4 qv = ((const float4*)q)[lane];
        float4 kv = ((const float4*)kk)[lane];
        float aq = wv.x * qv.x + wv.y * qv.y + wv.z * qv.z + wv.w * qv.w;
        float ak = wv.x * kv.x + wv.y * kv.y + wv.z * kv.z + wv.w * kv.w;
#pragma unroll
        for (int off = 16; off; off >>= 1) {
            aq += __shfl_xor_sync(0xffffffffu, aq, off);
            ak += __shfl_xor_sync(0xffffffffu, ak, off);
        }
        if (lane == 0) { g_wq[gw] = aq; g_wk[gw] = ak; }
    } else if (gw == RELS * C) {
        float p = 0.f;
        for (int o = lane; o < C; o += 32) p += le[o] * ee[o];
#pragma unroll
        for (int off = 16; off; off >>= 1) p += __shfl_xor_sync(0xffffffffu, p, off);
        if (lane == 0) g_cattr = p;
    }
}

// ---------------- per-node attention scalars ----------------
__global__ void k_sqk(const float* __restrict__ x, int n) {
    int gw = (blockIdx.x * blockDim.x + threadIdx.x) >> 5;
    int lane = threadIdx.x & 31;
    if (gw >= n) return;
    float4 xv = ((const float4*)x)[(size_t)gw * 32 + lane];
    float aq[RELS], ak[RELS];
#pragma unroll
    for (int r = 0; r < RELS; ++r) {
        float4 wqv = ((const float4*)g_wq)[r * 32 + lane];
        float4 wkv = ((const float4*)g_wk)[r * 32 + lane];
        aq[r] = xv.x * wqv.x + xv.y * wqv.y + xv.z * wqv.z + xv.w * wqv.w;
        ak[r] = xv.x * wkv.x + xv.y * wkv.y + xv.z * wkv.z + xv.w * wkv.w;
    }
#pragma unroll
    for (int off = 16; off; off >>= 1) {
#pragma unroll
        for (int r = 0; r < RELS; ++r) {
            aq[r] += __shfl_xor_sync(0xffffffffu, aq[r], off);
            ak[r] += __shfl_xor_sync(0xffffffffu, ak[r], off);
        }
    }
    if (lane == 0) {
#pragma unroll
        for (int r = 0; r < RELS; ++r) {
            g_sq[r * n + gw] = aq[r];
            g_sk[r * n + gw] = ak[r];
        }
    }
}

// ---------------- GEMM with packed f32x2 FMA: g_xw[r] = X @ W[r] ----------------
__global__ __launch_bounds__(256, 2) void k_gemm(const float* __restrict__ X,
                                                 const float* __restrict__ W, int n) {
    const int BK = 32;
    __shared__ float As[BK][132];   // transposed A tile: As[k][m], padded
    __shared__ float Bs[BK][128];

    int r = blockIdx.y;
    int m0 = blockIdx.x * 128;
    const float* Wr = W + (size_t)r * C * C;
    float* Cr = g_xw + ((size_t)r * n + m0) * C;

    int tid = threadIdx.x;
    int tx = tid & 15, ty = tid >> 4;

    unsigned long long acc[8][4];   // packed (j, j+1) fp32 pairs
#pragma unroll
    for (int i = 0; i < 8; ++i)
#pragma unroll
        for (int j = 0; j < 4; ++j) acc[i][j] = 0ull;

    for (int kc = 0; kc < C; kc += BK) {
#pragma unroll
        for (int t = 0; t < 4; ++t) {
            int row = (tid >> 3) + t * 32;
            int kofs = (tid & 7) << 2;
            float4 v = make_float4(0.f, 0.f, 0.f, 0.f);
            if (m0 + row < n)
                v = *(const float4*)(X + (size_t)(m0 + row) * C + kc + kofs);
            As[kofs + 0][row] = v.x;
            As[kofs + 1][row] = v.y;
            As[kofs + 2][row] = v.z;
            As[kofs + 3][row] = v.w;
        }
#pragma unroll
        for (int t = 0; t < 4; ++t) {
            int kkx = (tid >> 5) + t * 8;
            int col = (tid & 31) << 2;
            *(float4*)&Bs[kkx][col] = *(const float4*)(Wr + (size_t)(kc + kkx) * C + col);
        }
        __syncthreads();
#pragma unroll
        for (int k = 0; k < BK; ++k) {
            F4U2 a0, a1, b0, b1;
            a0.f = *(const float4*)&As[k][ty * 8];
            a1.f = *(const float4*)&As[k][ty * 8 + 4];
            b0.f = *(const float4*)&Bs[k][tx * 8];
            b1.f = *(const float4*)&Bs[k][tx * 8 + 4];
            unsigned long long bp[4] = { b0.u[0], b0.u[1], b1.u[0], b1.u[1] };
            float av[8] = { a0.f.x, a0.f.y, a0.f.z, a0.f.w,
                            a1.f.x, a1.f.y, a1.f.z, a1.f.w };
#pragma unroll
            for (int i = 0; i < 8; ++i) {
                unsigned long long ap;
                asm("mov.b64 %0, {%1, %1};" : "=l"(ap) : "f"(av[i]));
#pragma unroll
                for (int j = 0; j < 4; ++j)
                    asm("fma.rn.f32x2 %0, %1, %2, %0;"
                        : "+l"(acc[i][j]) : "l"(ap), "l"(bp[j]));
            }
        }
        __syncthreads();
    }
#pragma unroll
    for (int i = 0; i < 8; ++i) {
        int row = m0 + ty * 8 + i;
        if (row < n) {
            float* crow = Cr + (size_t)(ty * 8 + i) * C + tx * 8;
            F4U2 o0, o1;
            o0.u[0] = acc[i][0]; o0.u[1] = acc[i][1];
            o1.u[0] = acc[i][2]; o1.u[1] = acc[i][3];
            *(float4*)(crow)     = o0.f;
            *(float4*)(crow + 4) = o1.f;
        }
    }
}

// ---------------- per-edge attention logits ----------------
__global__ void k_alpha(const int* __restrict__ src, const int* __restrict__ dst,
                        const int* __restrict__ etype, const float* __restrict__ attr,
                        int n, int e_cnt) {
    int e = blockIdx.x * blockDim.x + threadIdx.x;
    if (e >= e_cnt) return;
    int r = etype[e];
    float a = g_sq[r * n + dst[e]] + g_sk[r * n + src[e]] + g_cattr * attr[e];
    g_alpha[e] = (a > 0.f) ? a : 0.2f * a;
}

// ---------------- per-node softmax + weighted aggregation (warp per node) ----------------
__global__ void k_agg(const int* __restrict__ src, const int* __restrict__ etype,
                      const float* __restrict__ bias, float* __restrict__ out,
                      int relu, int n) {
    int gw = (blockIdx.x * blockDim.x + threadIdx.x) >> 5;
    int lane = threadIdx.x & 31;
    if (gw >= n) return;
    int beg = g_indptr[gw], end = g_indptr[gw + 1];

    float m = -CUDART_INF_F;
    for (int j = beg + lane; j < end; j += 32) m = fmaxf(m, g_alpha[g_eidx[j]]);
#pragma unroll
    for (int off = 16; off; off >>= 1) m = fmaxf(m, __shfl_xor_sync(0xffffffffu, m, off));

    float s = 0.f;
    for (int j = beg + lane; j < end; j += 32) s += __expf(g_alpha[g_eidx[j]] - m);
#pragma unroll
    for (int off = 16; off; off >>= 1) s += __shfl_xor_sync(0xffffffffu, s, off);
    float inv = 1.f / (s + 1e-16f);

    float4 acc = make_float4(0.f, 0.f, 0.f, 0.f);
    for (int j = beg; j < end; ++j) {
        int e = g_eidx[j];
        float coeff = __expf(g_alpha[e] - m) * inv;
        int sv = src[e];
        int r = etype[e];
        const float4* row = (const float4*)(g_xw + ((size_t)r * n + sv) * C);
        float4 v = row[lane];
        acc.x = fmaf(coeff, v.x, acc.x);
        acc.y = fmaf(coeff, v.y, acc.y);
        acc.z = fmaf(coeff, v.z, acc.z);
        acc.w = fmaf(coeff, v.w, acc.w);
    }
    float4 bb = ((const float4*)bias)[lane];
    acc.x += bb.x; acc.y += bb.y; acc.z += bb.z; acc.w += bb.w;
    if (relu) {
        acc.x = fmaxf(acc.x, 0.f); acc.y = fmaxf(acc.y, 0.f);
        acc.z = fmaxf(acc.z, 0.f); acc.w = fmaxf(acc.w, 0.f);
    }
    ((float4*)(out + (size_t)gw * C))[lane] = acc;
}

// ---------------- driver ----------------
extern "C" void kernel_launch(void* const* d_in, const int* in_sizes, int n_in,
                              void* d_out, int out_size) {
    const float* x    = (const float*)d_in[0];
    const int*   ei   = (const int*)d_in[1];
    const int*   et   = (const int*)d_in[2];
    const float* attr = (const float*)d_in[3];
    const float *w1 = (const float*)d_in[4],  *q1 = (const float*)d_in[5],
                *k1 = (const float*)d_in[6],  *le1 = (const float*)d_in[7],
                *e1 = (const float*)d_in[8],  *b1 = (const float*)d_in[9];
    const float *w2 = (const float*)d_in[10], *q2 = (const float*)d_in[11],
                *k2 = (const float*)d_in[12], *le2 = (const float*)d_in[13],
                *e2 = (const float*)d_in[14], *b2 = (const float*)d_in[15];

    int n = in_sizes[0] / C;
    int e_cnt = in_sizes[2];
    const int* src = ei;
    const int* dst = ei + e_cnt;

    float* h = nullptr;
    cudaGetSymbolAddress((void**)&h, g_h);

    dim3 gg((n + 127) / 128, RELS);
    int nblk = (n + 1023) / 1024;
    int prep_blocks = (RELS * C + 1 + 7) / 8;  // warps of 8 per block

    // CSR build interleaved with layer-1 GEMM (independent)
    k_zero_deg<<<(n + 255) / 256, 256>>>(n);
    k_count<<<(e_cnt + 255) / 256, 256>>>(dst, e_cnt);
    k_scanA<<<nblk, 1024>>>(n);
    k_gemm<<<gg, 256>>>(x, w1, n);                 // big kernel early for ncu
    k_scanB<<<1, 64>>>(nblk);
    k_scanC<<<(n + 255) / 256, 256>>>(n);
    k_fill<<<(e_cnt + 255) / 256, 256>>>(dst, e_cnt);

    // layer 1 attention + aggregation
    k_prep<<<prep_blocks, 256>>>(w1, q1, k1, le1, e1);
    k_sqk<<<(n + 7) / 8, 256>>>(x, n);
    k_alpha<<<(e_cnt + 255) / 256, 256>>>(src, dst, et, attr, n, e_cnt);
    k_agg<<<(n + 7) / 8, 256>>>(src, et, b1, h, 1, n);

    // layer 2
    k_gemm<<<gg, 256>>>(h, w2, n);
    k_prep<<<prep_blocks, 256>>>(w2, q2, k2, le2, e2);
    k_sqk<<<(n + 7) / 8, 256>>>(h, n);
    k_alpha<<<(e_cnt + 255) / 256, 256>>>(src, dst, et, attr, n, e_cnt);
    k_agg<<<(n + 7) / 8, 256>>>(src, et, b2, (float*)d_out, 0, n);
}

// round 4
// speedup vs baseline: 1.2755x; 1.1281x over previous
#include <cuda_runtime.h>
#include <math_constants.h>
#include <cstdint>

#define MAXN 50000
#define MAXE 500000
#define C    128
#define RELS 3

// ---------------- scratch (static device memory; no allocation) ----------------
__device__ __align__(16) float g_xw[(size_t)RELS * MAXN * C];
__device__ __align__(16) float g_h[(size_t)MAXN * C];
__device__ float g_alpha[MAXE];
__device__ float g_sq[RELS * MAXN];
__device__ float g_sk[RELS * MAXN];
__device__ __align__(16) float g_wq[RELS * C];
__device__ __align__(16) float g_wk[RELS * C];
__device__ float g_cattr;
__device__ int   g_deg[MAXN];
__device__ int   g_incl[MAXN];
__device__ int   g_indptr[MAXN + 1];
__device__ int   g_cursor[MAXN];
__device__ int   g_eidx[MAXE];
__device__ int   g_bsum[64];

__device__ __forceinline__ float tf32_rna(float v) {
    float r;
    asm("cvt.rna.tf32.f32 %0, %1;" : "=f"(r) : "f"(v));
    return r;
}
__device__ __forceinline__ void mma_tf32(float* c, const uint32_t* a, const uint32_t* b) {
    asm volatile(
        "mma.sync.aligned.m16n8k8.row.col.f32.tf32.tf32.f32 "
        "{%0,%1,%2,%3}, {%4,%5,%6,%7}, {%8,%9}, {%0,%1,%2,%3};"
        : "+f"(c[0]), "+f"(c[1]), "+f"(c[2]), "+f"(c[3])
        : "r"(a[0]), "r"(a[1]), "r"(a[2]), "r"(a[3]), "r"(b[0]), "r"(b[1]));
}

// ---------------- CSR build ----------------
__global__ void k_zero_deg(int n) {
    int i = blockIdx.x * blockDim.x + threadIdx.x;
    if (i < n) g_deg[i] = 0;
}
__global__ void k_count(const int* __restrict__ dst, int e_cnt) {
    int e = blockIdx.x * blockDim.x + threadIdx.x;
    if (e < e_cnt) atomicAdd(&g_deg[dst[e]], 1);
}
__global__ void k_scanA(int n) {
    __shared__ int sh[2][1024];
    int tid = threadIdx.x;
    int i = blockIdx.x * 1024 + tid;
    int v = (i < n) ? g_deg[i] : 0;
    sh[0][tid] = v;
    __syncthreads();
    int pb = 0;
#pragma unroll
    for (int off = 1; off < 1024; off <<= 1) {
        int nb = pb ^ 1;
        int val = sh[pb][tid];
        if (tid >= off) val += sh[pb][tid - off];
        sh[nb][tid] = val;
        pb = nb;
        __syncthreads();
    }
    int incl = sh[pb][tid];
    if (i < n) g_incl[i] = incl;
    if (tid == 1023) g_bsum[blockIdx.x] = incl;
}
__global__ void k_scanB(int nblk) {
    __shared__ int sh[64];
    int t = threadIdx.x;
    int v = (t < nblk) ? g_bsum[t] : 0;
    sh[t] = v;
    __syncthreads();
#pragma unroll
    for (int off = 1; off < 64; off <<= 1) {
        int add = (t >= off) ? sh[t - off] : 0;
        __syncthreads();
        sh[t] += add;
        __syncthreads();
    }
    if (t < nblk) g_bsum[t] = sh[t] - v;
}
__global__ void k_scanC(int n) {
    int i = blockIdx.x * blockDim.x + threadIdx.x;
    if (i < n) {
        int total = g_incl[i] + g_bsum[i >> 10];
        g_indptr[i + 1] = total;
        g_cursor[i] = total - g_deg[i];
        if (i == 0) g_indptr[0] = 0;
    }
}
__global__ void k_fill(const int* __restrict__ dst, int e_cnt) {
    int e = blockIdx.x * blockDim.x + threadIdx.x;
    if (e < e_cnt) {
        int pos = atomicAdd(&g_cursor[dst[e]], 1);
        g_eidx[pos] = e;
    }
}

// ---------------- per-layer precompute ----------------
__global__ void k_prep(const float* __restrict__ w, const float* __restrict__ q,
                       const float* __restrict__ kk, const float* __restrict__ le,
                       const float* __restrict__ ee) {
    int gw = (blockIdx.x * blockDim.x + threadIdx.x) >> 5;
    int lane = threadIdx.x & 31;
    if (gw < RELS * C) {
        const float4* row = (const float4*)(w + (size_t)gw * C);
        float4 wv = row[lane];
        float4 qv = ((const float4*)q)[lane];
        float4 kv = ((const float4*)kk)[lane];
        float aq = wv.x * qv.x + wv.y * qv.y + wv.z * qv.z + wv.w * qv.w;
        float ak = wv.x * kv.x + wv.y * kv.y + wv.z * kv.z + wv.w * kv.w;
#pragma unroll
        for (int off = 16; off; off >>= 1) {
            aq += __shfl_xor_sync(0xffffffffu, aq, off);
            ak += __shfl_xor_sync(0xffffffffu, ak, off);
        }
        if (lane == 0) { g_wq[gw] = aq; g_wk[gw] = ak; }
    } else if (gw == RELS * C) {
        float p = 0.f;
        for (int o = lane; o < C; o += 32) p += le[o] * ee[o];
#pragma unroll
        for (int off = 16; off; off >>= 1) p += __shfl_xor_sync(0xffffffffu, p, off);
        if (lane == 0) g_cattr = p;
    }
}

// ---------------- per-node attention scalars ----------------
__global__ void k_sqk(const float* __restrict__ x, int n) {
    int gw = (blockIdx.x * blockDim.x + threadIdx.x) >> 5;
    int lane = threadIdx.x & 31;
    if (gw >= n) return;
    float4 xv = ((const float4*)x)[(size_t)gw * 32 + lane];
    float aq[RELS], ak[RELS];
#pragma unroll
    for (int r = 0; r < RELS; ++r) {
        float4 wqv = ((const float4*)g_wq)[r * 32 + lane];
        float4 wkv = ((const float4*)g_wk)[r * 32 + lane];
        aq[r] = xv.x * wqv.x + xv.y * wqv.y + xv.z * wqv.z + xv.w * wqv.w;
        ak[r] = xv.x * wkv.x + xv.y * wkv.y + xv.z * wkv.z + xv.w * wkv.w;
    }
#pragma unroll
    for (int off = 16; off; off >>= 1) {
#pragma unroll
        for (int r = 0; r < RELS; ++r) {
            aq[r] += __shfl_xor_sync(0xffffffffu, aq[r], off);
            ak[r] += __shfl_xor_sync(0xffffffffu, ak[r], off);
        }
    }
    if (lane == 0) {
#pragma unroll
        for (int r = 0; r < RELS; ++r) {
            g_sq[r * n + gw] = aq[r];
            g_sk[r * n + gw] = ak[r];
        }
    }
}

// ---------------- HMMA tf32 3-term GEMM: g_xw[r] = X @ W[r] ----------------
// CTA: 256 thr (8 warps), tile M=128 x N=128, K chunked 64.
// smem floats: A_hi[128*68], A_lo[128*68], B_hi[64*132], B_lo[64*132]
#define APAD 68
#define BPAD 132
#define AH_OFF 0
#define AL_OFF (128 * APAD)
#define BH_OFF (2 * 128 * APAD)
#define BL_OFF (2 * 128 * APAD + 64 * BPAD)
#define GEMM_SMEM ((2 * 128 * APAD + 2 * 64 * BPAD) * 4)

__global__ __launch_bounds__(256, 1) void k_gemm_mma(const float* __restrict__ X,
                                                     const float* __restrict__ W, int n) {
    extern __shared__ float sm[];
    float* Ah = sm + AH_OFF;
    float* Al = sm + AL_OFF;
    float* Bh = sm + BH_OFF;
    float* Bl = sm + BL_OFF;

    int r = blockIdx.y;
    int m0 = blockIdx.x * 128;
    const float* Wr = W + (size_t)r * C * C;
    float* Cr = g_xw + ((size_t)r * n) * C;

    int tid = threadIdx.x;
    int lane = tid & 31;
    int wid = tid >> 5;
    int wm = wid & 1;       // 0..1 : 64-row half
    int wn = wid >> 1;      // 0..3 : 32-col quarter

    float acc[4][4][4];
#pragma unroll
    for (int a = 0; a < 4; ++a)
#pragma unroll
        for (int b = 0; b < 4; ++b)
#pragma unroll
            for (int cc = 0; cc < 4; ++cc) acc[a][b][cc] = 0.f;

    for (int kc = 0; kc < C; kc += 64) {
        // ---- load + split A: 128 rows x 64 k ----
        {
            int k4 = (tid & 15) * 4;
            int rb = tid >> 4;          // 0..15
#pragma unroll
            for (int it = 0; it < 8; ++it) {
                int row = rb + it * 16;
                float4 v = make_float4(0.f, 0.f, 0.f, 0.f);
                if (m0 + row < n)
                    v = *(const float4*)(X + (size_t)(m0 + row) * C + kc + k4);
                float4 hi, lo;
                hi.x = tf32_rna(v.x); lo.x = tf32_rna(v.x - hi.x);
                hi.y = tf32_rna(v.y); lo.y = tf32_rna(v.y - hi.y);
                hi.z = tf32_rna(v.z); lo.z = tf32_rna(v.z - hi.z);
                hi.w = tf32_rna(v.w); lo.w = tf32_rna(v.w - hi.w);
                *(float4*)(Ah + row * APAD + k4) = hi;
                *(float4*)(Al + row * APAD + k4) = lo;
            }
        }
        // ---- load + split B: 64 k-rows x 128 n (k-major) ----
        {
            int n4 = (tid & 31) * 4;
            int kb = tid >> 5;          // 0..7
#pragma unroll
            for (int it = 0; it < 8; ++it) {
                int krow = kb + it * 8;
                float4 v = *(const float4*)(Wr + (size_t)(kc + krow) * C + n4);
                float4 hi, lo;
                hi.x = tf32_rna(v.x); lo.x = tf32_rna(v.x - hi.x);
                hi.y = tf32_rna(v.y); lo.y = tf32_rna(v.y - hi.y);
                hi.z = tf32_rna(v.z); lo.z = tf32_rna(v.z - hi.z);
                hi.w = tf32_rna(v.w); lo.w = tf32_rna(v.w - hi.w);
                *(float4*)(Bh + krow * BPAD + n4) = hi;
                *(float4*)(Bl + krow * BPAD + n4) = lo;
            }
        }
        __syncthreads();

#pragma unroll
        for (int ks = 0; ks < 8; ++ks) {
            int ka = ks * 8 + (lane & 3);
            int ra = wm * 64 + (lane >> 2);
            uint32_t ah[4][4], al[4][4];
#pragma unroll
            for (int mt = 0; mt < 4; ++mt) {
                int r0 = ra + mt * 16;
                ah[mt][0] = __float_as_uint(Ah[r0 * APAD + ka]);
                ah[mt][1] = __float_as_uint(Ah[(r0 + 8) * APAD + ka]);
                ah[mt][2] = __float_as_uint(Ah[r0 * APAD + ka + 4]);
                ah[mt][3] = __float_as_uint(Ah[(r0 + 8) * APAD + ka + 4]);
                al[mt][0] = __float_as_uint(Al[r0 * APAD + ka]);
                al[mt][1] = __float_as_uint(Al[(r0 + 8) * APAD + ka]);
                al[mt][2] = __float_as_uint(Al[r0 * APAD + ka + 4]);
                al[mt][3] = __float_as_uint(Al[(r0 + 8) * APAD + ka + 4]);
            }
            uint32_t bh[4][2], bl[4][2];
            int kb = ks * 8 + (lane & 3);
            int nb0 = wn * 32 + (lane >> 2);
#pragma unroll
            for (int nt = 0; nt < 4; ++nt) {
                int nn = nb0 + nt * 8;
                bh[nt][0] = __float_as_uint(Bh[kb * BPAD + nn]);
                bh[nt][1] = __float_as_uint(Bh[(kb + 4) * BPAD + nn]);
                bl[nt][0] = __float_as_uint(Bl[kb * BPAD + nn]);
                bl[nt][1] = __float_as_uint(Bl[(kb + 4) * BPAD + nn]);
            }
#pragma unroll
            for (int mt = 0; mt < 4; ++mt)
#pragma unroll
                for (int nt = 0; nt < 4; ++nt) {
                    mma_tf32(acc[mt][nt], ah[mt], bh[nt]);
                    mma_tf32(acc[mt][nt], ah[mt], bl[nt]);
                    mma_tf32(acc[mt][nt], al[mt], bh[nt]);
                }
        }
        __syncthreads();
    }

    // ---- epilogue ----
#pragma unroll
    for (int mt = 0; mt < 4; ++mt) {
        int row0 = m0 + wm * 64 + mt * 16 + (lane >> 2);
        int row1 = row0 + 8;
#pragma unroll
        for (int nt = 0; nt < 4; ++nt) {
            int col = wn * 32 + nt * 8 + 2 * (lane & 3);
            if (row0 < n)
                *(float2*)(Cr + (size_t)row0 * C + col) = make_float2(acc[mt][nt][0], acc[mt][nt][1]);
            if (row1 < n)
                *(float2*)(Cr + (size_t)row1 * C + col) = make_float2(acc[mt][nt][2], acc[mt][nt][3]);
        }
    }
}

// ---------------- per-edge attention logits ----------------
__global__ void k_alpha(const int* __restrict__ src, const int* __restrict__ dst,
                        const int* __restrict__ etype, const float* __restrict__ attr,
                        int n, int e_cnt) {
    int e = blockIdx.x * blockDim.x + threadIdx.x;
    if (e >= e_cnt) return;
    int r = etype[e];
    float a = g_sq[r * n + dst[e]] + g_sk[r * n + src[e]] + g_cattr * attr[e];
    g_alpha[e] = (a > 0.f) ? a : 0.2f * a;
}

// ---------------- per-node softmax + weighted aggregation (warp per node) ----------------
__global__ void k_agg(const int* __restrict__ src, const int* __restrict__ etype,
                      const float* __restrict__ bias, float* __restrict__ out,
                      int relu, int n) {
    int gw = (blockIdx.x * blockDim.x + threadIdx.x) >> 5;
    int lane = threadIdx.x & 31;
    if (gw >= n) return;
    int beg = g_indptr[gw], end = g_indptr[gw + 1];

    float m = -CUDART_INF_F;
    for (int j = beg + lane; j < end; j += 32) m = fmaxf(m, g_alpha[g_eidx[j]]);
#pragma unroll
    for (int off = 16; off; off >>= 1) m = fmaxf(m, __shfl_xor_sync(0xffffffffu, m, off));

    float s = 0.f;
    for (int j = beg + lane; j < end; j += 32) s += __expf(g_alpha[g_eidx[j]] - m);
#pragma unroll
    for (int off = 16; off; off >>= 1) s += __shfl_xor_sync(0xffffffffu, s, off);
    float inv = 1.f / (s + 1e-16f);

    float4 acc = make_float4(0.f, 0.f, 0.f, 0.f);
    for (int j = beg; j < end; ++j) {
        int e = g_eidx[j];
        float coeff = __expf(g_alpha[e] - m) * inv;
        int sv = src[e];
        int r = etype[e];
        const float4* row = (const float4*)(g_xw + ((size_t)r * n + sv) * C);
        float4 v = row[lane];
        acc.x = fmaf(coeff, v.x, acc.x);
        acc.y = fmaf(coeff, v.y, acc.y);
        acc.z = fmaf(coeff, v.z, acc.z);
        acc.w = fmaf(coeff, v.w, acc.w);
    }
    float4 bb = ((const float4*)bias)[lane];
    acc.x += bb.x; acc.y += bb.y; acc.z += bb.z; acc.w += bb.w;
    if (relu) {
        acc.x = fmaxf(acc.x, 0.f); acc.y = fmaxf(acc.y, 0.f);
        acc.z = fmaxf(acc.z, 0.f); acc.w = fmaxf(acc.w, 0.f);
    }
    ((float4*)(out + (size_t)gw * C))[lane] = acc;
}

// ---------------- driver ----------------
extern "C" void kernel_launch(void* const* d_in, const int* in_sizes, int n_in,
                              void* d_out, int out_size) {
    const float* x    = (const float*)d_in[0];
    const int*   ei   = (const int*)d_in[1];
    const int*   et   = (const int*)d_in[2];
    const float* attr = (const float*)d_in[3];
    const float *w1 = (const float*)d_in[4],  *q1 = (const float*)d_in[5],
                *k1 = (const float*)d_in[6],  *le1 = (const float*)d_in[7],
                *e1 = (const float*)d_in[8],  *b1 = (const float*)d_in[9];
    const float *w2 = (const float*)d_in[10], *q2 = (const float*)d_in[11],
                *k2 = (const float*)d_in[12], *le2 = (const float*)d_in[13],
                *e2 = (const float*)d_in[14], *b2 = (const float*)d_in[15];

    int n = in_sizes[0] / C;
    int e_cnt = in_sizes[2];
    const int* src = ei;
    const int* dst = ei + e_cnt;

    float* h = nullptr;
    cudaGetSymbolAddress((void**)&h, g_h);

    static bool attr_set = false;
    if (!attr_set) {
        cudaFuncSetAttribute(k_gemm_mma, cudaFuncAttributeMaxDynamicSharedMemorySize, GEMM_SMEM);
        attr_set = true;
    }

    dim3 gg((n + 127) / 128, RELS);
    int nblk = (n + 1023) / 1024;
    int prep_blocks = (RELS * C + 1 + 7) / 8;

    // CSR build interleaved with layer-1 GEMM (independent)
    k_zero_deg<<<(n + 255) / 256, 256>>>(n);
    k_count<<<(e_cnt + 255) / 256, 256>>>(dst, e_cnt);
    k_scanA<<<nblk, 1024>>>(n);
    k_gemm_mma<<<gg, 256, GEMM_SMEM>>>(x, w1, n);
    k_scanB<<<1, 64>>>(nblk);
    k_scanC<<<(n + 255) / 256, 256>>>(n);
    k_fill<<<(e_cnt + 255) / 256, 256>>>(dst, e_cnt);

    // layer 1 attention + aggregation
    k_prep<<<prep_blocks, 256>>>(w1, q1, k1, le1, e1);
    k_sqk<<<(n + 7) / 8, 256>>>(x, n);
    k_alpha<<<(e_cnt + 255) / 256, 256>>>(src, dst, et, attr, n, e_cnt);
    k_agg<<<(n + 7) / 8, 256>>>(src, et, b1, h, 1, n);

    // layer 2
    k_gemm_mma<<<gg, 256, GEMM_SMEM>>>(h, w2, n);
    k_prep<<<prep_blocks, 256>>>(w2, q2, k2, le2, e2);
    k_sqk<<<(n + 7) / 8, 256>>>(h, n);
    k_alpha<<<(e_cnt + 255) / 256, 256>>>(src, dst, et, attr, n, e_cnt);
    k_agg<<<(n + 7) / 8, 256>>>(src, et, b2, (float*)d_out, 0, n);
}

// round 5
// speedup vs baseline: 1.2907x; 1.0120x over previous
#include <cuda_runtime.h>
#include <cuda_bf16.h>
#include <math_constants.h>
#include <cstdint>

#define MAXN 50000
#define MAXE 500000
#define C    128
#define RELS 3

// ---------------- scratch (static device memory; no allocation) ----------------
__device__ __align__(16) float g_xw[(size_t)RELS * MAXN * C];
__device__ __align__(16) float g_h[(size_t)MAXN * C];
__device__ float g_alpha[MAXE];
__device__ float g_sq[RELS * MAXN];
__device__ float g_sk[RELS * MAXN];
__device__ __align__(16) float g_wq[RELS * C];
__device__ __align__(16) float g_wk[RELS * C];
__device__ float g_cattr;
__device__ __align__(16) __nv_bfloat16 g_wt_hi[RELS * C * C];  // W^T split hi [r][n][k]
__device__ __align__(16) __nv_bfloat16 g_wt_lo[RELS * C * C];  // W^T split lo [r][n][k]
__device__ int   g_deg[MAXN];
__device__ int   g_incl[MAXN];
__device__ int   g_indptr[MAXN + 1];
__device__ int   g_cursor[MAXN];
__device__ int   g_eidx[MAXE];
__device__ int   g_bsum[64];

__device__ __forceinline__ void mma_bf16(float* c, const uint32_t* a, const uint32_t* b) {
    asm volatile(
        "mma.sync.aligned.m16n8k16.row.col.f32.bf16.bf16.f32 "
        "{%0,%1,%2,%3}, {%4,%5,%6,%7}, {%8,%9}, {%0,%1,%2,%3};"
        : "+f"(c[0]), "+f"(c[1]), "+f"(c[2]), "+f"(c[3])
        : "r"(a[0]), "r"(a[1]), "r"(a[2]), "r"(a[3]), "r"(b[0]), "r"(b[1]));
}

// ---------------- CSR build ----------------
__global__ void k_zero_deg(int n) {
    int i = blockIdx.x * blockDim.x + threadIdx.x;
    if (i < n) g_deg[i] = 0;
}
__global__ void k_count(const int* __restrict__ dst, int e_cnt) {
    int e = blockIdx.x * blockDim.x + threadIdx.x;
    if (e < e_cnt) atomicAdd(&g_deg[dst[e]], 1);
}
__global__ void k_scanA(int n) {
    __shared__ int sh[2][1024];
    int tid = threadIdx.x;
    int i = blockIdx.x * 1024 + tid;
    int v = (i < n) ? g_deg[i] : 0;
    sh[0][tid] = v;
    __syncthreads();
    int pb = 0;
#pragma unroll
    for (int off = 1; off < 1024; off <<= 1) {
        int nb = pb ^ 1;
        int val = sh[pb][tid];
        if (tid >= off) val += sh[pb][tid - off];
        sh[nb][tid] = val;
        pb = nb;
        __syncthreads();
    }
    int incl = sh[pb][tid];
    if (i < n) g_incl[i] = incl;
    if (tid == 1023) g_bsum[blockIdx.x] = incl;
}
__global__ void k_scanB(int nblk) {
    __shared__ int sh[64];
    int t = threadIdx.x;
    int v = (t < nblk) ? g_bsum[t] : 0;
    sh[t] = v;
    __syncthreads();
#pragma unroll
    for (int off = 1; off < 64; off <<= 1) {
        int add = (t >= off) ? sh[t - off] : 0;
        __syncthreads();
        sh[t] += add;
        __syncthreads();
    }
    if (t < nblk) g_bsum[t] = sh[t] - v;
}
__global__ void k_scanC(int n) {
    int i = blockIdx.x * blockDim.x + threadIdx.x;
    if (i < n) {
        int total = g_incl[i] + g_bsum[i >> 10];
        g_indptr[i + 1] = total;
        g_cursor[i] = total - g_deg[i];
        if (i == 0) g_indptr[0] = 0;
    }
}
__global__ void k_fill(const int* __restrict__ dst, int e_cnt) {
    int e = blockIdx.x * blockDim.x + threadIdx.x;
    if (e < e_cnt) {
        int pos = atomicAdd(&g_cursor[dst[e]], 1);
        g_eidx[pos] = e;
    }
}

// ---------------- per-layer precompute ----------------
__global__ void k_prep(const float* __restrict__ w, const float* __restrict__ q,
                       const float* __restrict__ kk, const float* __restrict__ le,
                       const float* __restrict__ ee) {
    int gw = (blockIdx.x * blockDim.x + threadIdx.x) >> 5;
    int lane = threadIdx.x & 31;
    if (gw < RELS * C) {
        const float4* row = (const float4*)(w + (size_t)gw * C);
        float4 wv = row[lane];
        float4 qv = ((const float4*)q)[lane];
        float4 kv = ((const float4*)kk)[lane];
        float aq = wv.x * qv.x + wv.y * qv.y + wv.z * qv.z + wv.w * qv.w;
        float ak = wv.x * kv.x + wv.y * kv.y + wv.z * kv.z + wv.w * kv.w;
#pragma unroll
        for (int off = 16; off; off >>= 1) {
            aq += __shfl_xor_sync(0xffffffffu, aq, off);
            ak += __shfl_xor_sync(0xffffffffu, ak, off);
        }
        if (lane == 0) { g_wq[gw] = aq; g_wk[gw] = ak; }
    } else if (gw == RELS * C) {
        float p = 0.f;
        for (int o = lane; o < C; o += 32) p += le[o] * ee[o];
#pragma unroll
        for (int off = 16; off; off >>= 1) p += __shfl_xor_sync(0xffffffffu, p, off);
        if (lane == 0) g_cattr = p;
    }
}

// transpose + bf16-split W: g_wt_*[r][n][k] from W[r][k][n]
__global__ void k_prepw(const float* __restrict__ W) {
    int r = blockIdx.x;
    const float* Wr = W + (size_t)r * C * C;
    for (int idx = threadIdx.x; idx < C * C; idx += blockDim.x) {
        int k = idx >> 7, nn = idx & 127;
        float v = Wr[idx];
        __nv_bfloat16 h = __float2bfloat16(v);
        float lo = v - __bfloat162float(h);
        g_wt_hi[(size_t)r * C * C + nn * C + k] = h;
        g_wt_lo[(size_t)r * C * C + nn * C + k] = __float2bfloat16(lo);
    }
}

// ---------------- per-node attention scalars ----------------
__global__ void k_sqk(const float* __restrict__ x, int n) {
    int gw = (blockIdx.x * blockDim.x + threadIdx.x) >> 5;
    int lane = threadIdx.x & 31;
    if (gw >= n) return;
    float4 xv = ((const float4*)x)[(size_t)gw * 32 + lane];
    float aq[RELS], ak[RELS];
#pragma unroll
    for (int r = 0; r < RELS; ++r) {
        float4 wqv = ((const float4*)g_wq)[r * 32 + lane];
        float4 wkv = ((const float4*)g_wk)[r * 32 + lane];
        aq[r] = xv.x * wqv.x + xv.y * wqv.y + xv.z * wqv.z + xv.w * wqv.w;
        ak[r] = xv.x * wkv.x + xv.y * wkv.y + xv.z * wkv.z + xv.w * wkv.w;
    }
#pragma unroll
    for (int off = 16; off; off >>= 1) {
#pragma unroll
        for (int r = 0; r < RELS; ++r) {
            aq[r] += __shfl_xor_sync(0xffffffffu, aq[r], off);
            ak[r] += __shfl_xor_sync(0xffffffffu, ak[r], off);
        }
    }
    if (lane == 0) {
#pragma unroll
        for (int r = 0; r < RELS; ++r) {
            g_sq[r * n + gw] = aq[r];
            g_sk[r * n + gw] = ak[r];
        }
    }
}

// ---------------- HMMA bf16 3-term GEMM: g_xw[r] = X @ W[r] ----------------
// CTA: 256 thr (8 warps), tile M=128 x N=128, K chunked 64. 2 CTAs/SM.
#define APADB 72   // bf16 elements per smem row (64 data + 8 pad) -> frag loads bank==lane
#define GEMM_SMEM (4 * 128 * APADB * 2)

__global__ __launch_bounds__(256, 2) void k_gemm_bf(const float* __restrict__ X, int n) {
    extern __shared__ __nv_bfloat16 smb[];
    __nv_bfloat16* Ah = smb;
    __nv_bfloat16* Al = Ah + 128 * APADB;
    __nv_bfloat16* Bh = Al + 128 * APADB;
    __nv_bfloat16* Bl = Bh + 128 * APADB;

    int r = blockIdx.y;
    int m0 = blockIdx.x * 128;
    float* Cr = g_xw + ((size_t)r * n) * C;
    const __nv_bfloat16* WTh = g_wt_hi + (size_t)r * C * C;
    const __nv_bfloat16* WTl = g_wt_lo + (size_t)r * C * C;

    int tid = threadIdx.x;
    int lane = tid & 31;
    int wid = tid >> 5;
    int wm = wid & 1;       // 64-row half
    int wn = wid >> 1;      // 32-col quarter

    float acc[4][4][4];
#pragma unroll
    for (int a = 0; a < 4; ++a)
#pragma unroll
        for (int b = 0; b < 4; ++b)
#pragma unroll
            for (int cc = 0; cc < 4; ++cc) acc[a][b][cc] = 0.f;

    for (int kc = 0; kc < C; kc += 64) {
        // ---- load + split A: 128 rows x 64 k fp32 -> bf16 hi/lo ----
        {
            int k4 = (tid & 15) * 4;
            int rb = tid >> 4;
#pragma unroll
            for (int it = 0; it < 8; ++it) {
                int row = rb + it * 16;
                float4 v = make_float4(0.f, 0.f, 0.f, 0.f);
                if (m0 + row < n)
                    v = *(const float4*)(X + (size_t)(m0 + row) * C + kc + k4);
                __nv_bfloat16 hx = __float2bfloat16(v.x), hy = __float2bfloat16(v.y);
                __nv_bfloat16 hz = __float2bfloat16(v.z), hw = __float2bfloat16(v.w);
                __nv_bfloat162 h01 = __nv_bfloat162(hx, hy);
                __nv_bfloat162 h23 = __nv_bfloat162(hz, hw);
                __nv_bfloat162 l01 = __nv_bfloat162(__float2bfloat16(v.x - __bfloat162float(hx)),
                                                    __float2bfloat16(v.y - __bfloat162float(hy)));
                __nv_bfloat162 l23 = __nv_bfloat162(__float2bfloat16(v.z - __bfloat162float(hz)),
                                                    __float2bfloat16(v.w - __bfloat162float(hw)));
                *(__nv_bfloat162*)(Ah + row * APADB + k4)     = h01;
                *(__nv_bfloat162*)(Ah + row * APADB + k4 + 2) = h23;
                *(__nv_bfloat162*)(Al + row * APADB + k4)     = l01;
                *(__nv_bfloat162*)(Al + row * APADB + k4 + 2) = l23;
            }
        }
        // ---- load B (pre-split bf16, [n][k]) ----
        {
            int k4 = (tid & 15) * 4;
            int nb = tid >> 4;
#pragma unroll
            for (int it = 0; it < 8; ++it) {
                int nn = nb + it * 16;
                uint2 vh = *(const uint2*)(WTh + (size_t)nn * C + kc + k4);
                uint2 vl = *(const uint2*)(WTl + (size_t)nn * C + kc + k4);
                *(uint2*)(Bh + nn * APADB + k4) = vh;
                *(uint2*)(Bl + nn * APADB + k4) = vl;
            }
        }
        __syncthreads();

#pragma unroll
        for (int ks = 0; ks < 4; ++ks) {
            int kb = ks * 16 + (lane & 3) * 2;
            int arow = wm * 64 + (lane >> 2);
            int nb0 = wn * 32 + (lane >> 2);
            uint32_t ah[4][4], al[4][4], bh[4][2], bl[4][2];
#pragma unroll
            for (int mt = 0; mt < 4; ++mt) {
                const __nv_bfloat16* p = Ah + (arow + mt * 16) * APADB + kb;
                const __nv_bfloat16* q = Al + (arow + mt * 16) * APADB + kb;
                ah[mt][0] = *(const uint32_t*)(p);
                ah[mt][1] = *(const uint32_t*)(p + 8 * APADB);
                ah[mt][2] = *(const uint32_t*)(p + 8);
                ah[mt][3] = *(const uint32_t*)(p + 8 * APADB + 8);
                al[mt][0] = *(const uint32_t*)(q);
                al[mt][1] = *(const uint32_t*)(q + 8 * APADB);
                al[mt][2] = *(const uint32_t*)(q + 8);
                al[mt][3] = *(const uint32_t*)(q + 8 * APADB + 8);
            }
#pragma unroll
            for (int nt = 0; nt < 4; ++nt) {
                const __nv_bfloat16* p = Bh + (nb0 + nt * 8) * APADB + kb;
                const __nv_bfloat16* q = Bl + (nb0 + nt * 8) * APADB + kb;
                bh[nt][0] = *(const uint32_t*)(p);
                bh[nt][1] = *(const uint32_t*)(p + 8);
                bl[nt][0] = *(const uint32_t*)(q);
                bl[nt][1] = *(const uint32_t*)(q + 8);
            }
            // term-outer: 16 independent accumulators between dependent writes
#pragma unroll
            for (int mt = 0; mt < 4; ++mt)
#pragma unroll
                for (int nt = 0; nt < 4; ++nt) mma_bf16(acc[mt][nt], ah[mt], bh[nt]);
#pragma unroll
            for (int mt = 0; mt < 4; ++mt)
#pragma unroll
                for (int nt = 0; nt < 4; ++nt) mma_bf16(acc[mt][nt], ah[mt], bl[nt]);
#pragma unroll
            for (int mt = 0; mt < 4; ++mt)
#pragma unroll
                for (int nt = 0; nt < 4; ++nt) mma_bf16(acc[mt][nt], al[mt], bh[nt]);
        }
        __syncthreads();
    }

    // ---- epilogue ----
#pragma unroll
    for (int mt = 0; mt < 4; ++mt) {
        int row0 = m0 + wm * 64 + mt * 16 + (lane >> 2);
        int row1 = row0 + 8;
#pragma unroll
        for (int nt = 0; nt < 4; ++nt) {
            int col = wn * 32 + nt * 8 + 2 * (lane & 3);
            if (row0 < n)
                *(float2*)(Cr + (size_t)row0 * C + col) = make_float2(acc[mt][nt][0], acc[mt][nt][1]);
            if (row1 < n)
                *(float2*)(Cr + (size_t)row1 * C + col) = make_float2(acc[mt][nt][2], acc[mt][nt][3]);
        }
    }
}

// ---------------- per-edge attention logits ----------------
__global__ void k_alpha(const int* __restrict__ src, const int* __restrict__ dst,
                        const int* __restrict__ etype, const float* __restrict__ attr,
                        int n, int e_cnt) {
    int e = blockIdx.x * blockDim.x + threadIdx.x;
    if (e >= e_cnt) return;
    int r = etype[e];
    float a = g_sq[r * n + dst[e]] + g_sk[r * n + src[e]] + g_cattr * attr[e];
    g_alpha[e] = (a > 0.f) ? a : 0.2f * a;
}

// ---------------- per-node softmax + weighted aggregation (warp per node) ----------------
__global__ void k_agg(const int* __restrict__ src, const int* __restrict__ etype,
                      const float* __restrict__ bias, float* __restrict__ out,
                      int relu, int n) {
    int gw = (blockIdx.x * blockDim.x + threadIdx.x) >> 5;
    int lane = threadIdx.x & 31;
    if (gw >= n) return;
    int beg = g_indptr[gw], end = g_indptr[gw + 1];

    float m = -CUDART_INF_F;
    for (int j = beg + lane; j < end; j += 32) m = fmaxf(m, g_alpha[g_eidx[j]]);
#pragma unroll
    for (int off = 16; off; off >>= 1) m = fmaxf(m, __shfl_xor_sync(0xffffffffu, m, off));

    float s = 0.f;
    for (int j = beg + lane; j < end; j += 32) s += __expf(g_alpha[g_eidx[j]] - m);
#pragma unroll
    for (int off = 16; off; off >>= 1) s += __shfl_xor_sync(0xffffffffu, s, off);
    float inv = 1.f / (s + 1e-16f);

    float4 acc = make_float4(0.f, 0.f, 0.f, 0.f);
    for (int j = beg; j < end; ++j) {
        int e = g_eidx[j];
        float coeff = __expf(g_alpha[e] - m) * inv;
        int sv = src[e];
        int r = etype[e];
        const float4* row = (const float4*)(g_xw + ((size_t)r * n + sv) * C);
        float4 v = row[lane];
        acc.x = fmaf(coeff, v.x, acc.x);
        acc.y = fmaf(coeff, v.y, acc.y);
        acc.z = fmaf(coeff, v.z, acc.z);
        acc.w = fmaf(coeff, v.w, acc.w);
    }
    float4 bb = ((const float4*)bias)[lane];
    acc.x += bb.x; acc.y += bb.y; acc.z += bb.z; acc.w += bb.w;
    if (relu) {
        acc.x = fmaxf(acc.x, 0.f); acc.y = fmaxf(acc.y, 0.f);
        acc.z = fmaxf(acc.z, 0.f); acc.w = fmaxf(acc.w, 0.f);
    }
    ((float4*)(out + (size_t)gw * C))[lane] = acc;
}

// ---------------- driver ----------------
extern "C" void kernel_launch(void* const* d_in, const int* in_sizes, int n_in,
                              void* d_out, int out_size) {
    const float* x    = (const float*)d_in[0];
    const int*   ei   = (const int*)d_in[1];
    const int*   et   = (const int*)d_in[2];
    const float* attr = (const float*)d_in[3];
    const float *w1 = (const float*)d_in[4],  *q1 = (const float*)d_in[5],
                *k1 = (const float*)d_in[6],  *le1 = (const float*)d_in[7],
                *e1 = (const float*)d_in[8],  *b1 = (const float*)d_in[9];
    const float *w2 = (const float*)d_in[10], *q2 = (const float*)d_in[11],
                *k2 = (const float*)d_in[12], *le2 = (const float*)d_in[13],
                *e2 = (const float*)d_in[14], *b2 = (const float*)d_in[15];

    int n = in_sizes[0] / C;
    int e_cnt = in_sizes[2];
    const int* src = ei;
    const int* dst = ei + e_cnt;

    float* h = nullptr;
    cudaGetSymbolAddress((void**)&h, g_h);

    static bool attr_set = false;
    if (!attr_set) {
        cudaFuncSetAttribute(k_gemm_bf, cudaFuncAttributeMaxDynamicSharedMemorySize, GEMM_SMEM);
        attr_set = true;
    }

    dim3 gg((n + 127) / 128, RELS);
    int nblk = (n + 1023) / 1024;
    int prep_blocks = (RELS * C + 1 + 7) / 8;

    // CSR build interleaved with layer-1 weight prep + GEMM (independent)
    k_zero_deg<<<(n + 255) / 256, 256>>>(n);
    k_prepw<<<RELS, 256>>>(w1);
    k_count<<<(e_cnt + 255) / 256, 256>>>(dst, e_cnt);
    k_scanA<<<nblk, 1024>>>(n);
    k_gemm_bf<<<gg, 256, GEMM_SMEM>>>(x, n);
    k_scanB<<<1, 64>>>(nblk);
    k_scanC<<<(n + 255) / 256, 256>>>(n);
    k_fill<<<(e_cnt + 255) / 256, 256>>>(dst, e_cnt);

    // layer 1 attention + aggregation
    k_prep<<<prep_blocks, 256>>>(w1, q1, k1, le1, e1);
    k_sqk<<<(n + 7) / 8, 256>>>(x, n);
    k_alpha<<<(e_cnt + 255) / 256, 256>>>(src, dst, et, attr, n, e_cnt);
    k_agg<<<(n + 7) / 8, 256>>>(src, et, b1, h, 1, n);

    // layer 2
    k_prepw<<<RELS, 256>>>(w2);
    k_gemm_bf<<<gg, 256, GEMM_SMEM>>>(h, n);
    k_prep<<<prep_blocks, 256>>>(w2, q2, k2, le2, e2);
    k_sqk<<<(n + 7) / 8, 256>>>(h, n);
    k_alpha<<<(e_cnt + 255) / 256, 256>>>(src, dst, et, attr, n, e_cnt);
    k_agg<<<(n + 7) / 8, 256>>>(src, et, b2, (float*)d_out, 0, n);
}